// round 1
// baseline (speedup 1.0000x reference)
#include <cuda_runtime.h>
#include <math.h>

#define Bn   16
#define Nn   1024
#define Dn   128
#define CAP  256     // max edges per row (mean ~52, 29 sigma headroom)

// ---------------- scratch (static device globals; no allocation) ----------------
__device__ float d_h   [Bn*Nn*Dn];
__device__ float d_g   [Bn*Nn*Dn];
__device__ float d_hdot[Bn*Nn];
__device__ int   d_colidx[Bn*Nn*CAP];
__device__ float d_eval  [Bn*Nn*CAP];
__device__ int   d_rowcnt[Bn*Nn];
__device__ int   d_colcnt[Bn*Nn];
__device__ float d_colmax[Bn*Nn];
__device__ float d_colZ  [Bn*Nn];
__device__ float d_colinv[Bn*Nn];
__device__ float d_r1[Bn*Nn*Dn];
__device__ float d_r2[Bn*Nn*Dn];

__device__ __forceinline__ void atomicMaxFloat(float* addr, float v) {
    int* ai = (int*)addr;
    int old = __float_as_int(*addr);
    while (__int_as_float(old) < v) {
        int assumed = old;
        old = atomicCAS(ai, assumed, __float_as_int(v));
        if (old == assumed) break;
    }
}

// ---------------- init: zero column stats ----------------
__global__ void k_init() {
    int t = blockIdx.x * blockDim.x + threadIdx.x;
    if (t < Bn*Nn) { d_colcnt[t] = 0; d_colmax[t] = 0.0f; d_colZ[t] = 0.0f; }
}

// ---------------- h = xW^T + b ; g = hA ; hdot = h.gw1 + gb ----------------
#define HG_ROWS 32
#define HG_SMEM ((128*129 + 128*128 + 512 + 512 + 16)*4)

__global__ void k_hg(const float* __restrict__ x, const float* __restrict__ Ww,
                     const float* __restrict__ Wb, const float* __restrict__ Am,
                     const float* __restrict__ gw, const float* __restrict__ gb) {
    extern __shared__ float sm[];
    float* Wt  = sm;                 // [128][129]  W transposed, padded
    float* Ash = Wt + 128*129;       // [128][128]  A as-is
    float* xs  = Ash + 128*128;      // 4 x rows
    float* hs  = xs + 512;           // 4 h rows
    float* red = hs + 512;           // 16 reduction slots

    const int t = threadIdx.x;       // 128 threads
    for (int i = t; i < 128*128; i += 128) {
        int o = i >> 7, dd = i & 127;
        Wt[dd*129 + o] = Ww[i];      // transpose into padded smem
        Ash[i] = Am[i];
    }
    const float wbo = Wb[t];
    const float gwo = gw[t];
    const float gb0 = gb[0];
    const int rowbase = blockIdx.x * HG_ROWS;

    for (int grp = 0; grp < HG_ROWS/4; grp++) {
        __syncthreads();
        const int r0 = rowbase + grp*4;
        for (int j = t; j < 512; j += 128) xs[j] = x[(size_t)r0*Dn + j];
        __syncthreads();

        float a0 = wbo, a1 = wbo, a2 = wbo, a3 = wbo;
        #pragma unroll 8
        for (int dd = 0; dd < 128; dd++) {
            float w = Wt[dd*129 + t];
            a0 += xs[dd]*w; a1 += xs[128+dd]*w; a2 += xs[256+dd]*w; a3 += xs[384+dd]*w;
        }
        hs[t] = a0; hs[128+t] = a1; hs[256+t] = a2; hs[384+t] = a3;
        d_h[(size_t)(r0+0)*Dn + t] = a0;
        d_h[(size_t)(r0+1)*Dn + t] = a1;
        d_h[(size_t)(r0+2)*Dn + t] = a2;
        d_h[(size_t)(r0+3)*Dn + t] = a3;

        float p0 = a0*gwo, p1 = a1*gwo, p2 = a2*gwo, p3 = a3*gwo;
        #pragma unroll
        for (int off = 16; off; off >>= 1) {
            p0 += __shfl_xor_sync(~0u, p0, off);
            p1 += __shfl_xor_sync(~0u, p1, off);
            p2 += __shfl_xor_sync(~0u, p2, off);
            p3 += __shfl_xor_sync(~0u, p3, off);
        }
        int warp = t >> 5;
        if ((t & 31) == 0) { red[warp*4+0]=p0; red[warp*4+1]=p1; red[warp*4+2]=p2; red[warp*4+3]=p3; }
        __syncthreads();
        if (t < 4) {
            float sdot = red[t] + red[4+t] + red[8+t] + red[12+t];
            d_hdot[r0 + t] = sdot + gb0;
        }

        float g0 = 0.f, g1 = 0.f, g2 = 0.f, g3 = 0.f;
        #pragma unroll 8
        for (int dd = 0; dd < 128; dd++) {
            float a = Ash[dd*128 + t];
            g0 += hs[dd]*a; g1 += hs[128+dd]*a; g2 += hs[256+dd]*a; g3 += hs[384+dd]*a;
        }
        d_g[(size_t)(r0+0)*Dn + t] = g0;
        d_g[(size_t)(r0+1)*Dn + t] = g1;
        d_g[(size_t)(r0+2)*Dn + t] = g2;
        d_g[(size_t)(r0+3)*Dn + t] = g3;
    }
}

// ---------------- build padded CSR of adj + column edge counts ----------------
__global__ void k_build(const float* __restrict__ adj) {
    const int i = blockIdx.x, b = blockIdx.y;
    const int row = b*Nn + i;
    __shared__ int cnt;
    if (threadIdx.x == 0) cnt = 0;
    __syncthreads();
    const float* arow = adj + (size_t)row * Nn;
    for (int j = threadIdx.x; j < Nn; j += blockDim.x) {
        if (arow[j] > 0.0f) {
            int s = atomicAdd(&cnt, 1);
            if (s < CAP) d_colidx[(size_t)row*CAP + s] = j;
            atomicAdd(&d_colcnt[b*Nn + j], 1);
        }
    }
    __syncthreads();
    if (threadIdx.x == 0) d_rowcnt[row] = (cnt < CAP) ? cnt : CAP;
}

// ---------------- per-edge bilinear score + column max ----------------
__global__ void k_edgeE() {
    const int i = blockIdx.x, b = blockIdx.y;
    const int row = b*Nn + i;
    __shared__ float P[256];
    const int t = threadIdx.x;                // 128 threads
    P[t]       = d_g[(size_t)row*Dn + t];     // g_i
    P[128 + t] = d_h[(size_t)row*Dn + t];     // h_i
    __syncthreads();
    const int cnt  = d_rowcnt[row];
    const int warp = t >> 5, lane = t & 31;
    for (int s = warp; s < cnt; s += 4) {
        const int col = d_colidx[(size_t)row*CAP + s];
        const float4 h4 = *(const float4*)&d_h[((size_t)b*Nn + col)*Dn + lane*4];
        const float4 g4 = *(const float4*)&d_g[((size_t)b*Nn + col)*Dn + lane*4];
        float p = P[lane*4+0]*h4.x + P[lane*4+1]*h4.y + P[lane*4+2]*h4.z + P[lane*4+3]*h4.w
                + P[128+lane*4+0]*g4.x + P[128+lane*4+1]*g4.y
                + P[128+lane*4+2]*g4.z + P[128+lane*4+3]*g4.w;
        #pragma unroll
        for (int off = 16; off; off >>= 1) p += __shfl_xor_sync(~0u, p, off);
        if (lane == 0) {
            d_eval[(size_t)row*CAP + s] = p;
            atomicMaxFloat(&d_colmax[b*Nn + col], p);  // init 0 = implicit non-edge term
        }
    }
}

// ---------------- column Z accumulation ----------------
__global__ void k_edgeZ() {
    const int i = blockIdx.x, b = blockIdx.y;
    const int row = b*Nn + i;
    const int cnt = d_rowcnt[row];
    for (int s = threadIdx.x; s < cnt; s += 128) {
        const int col = d_colidx[(size_t)row*CAP + s];
        const float e = d_eval[(size_t)row*CAP + s];
        atomicAdd(&d_colZ[b*Nn + col], expf(e - d_colmax[b*Nn + col]));
    }
}

// ---------------- finalize column stats: Z += (N - cnt) * exp(-max) ----------------
__global__ void k_colfinal() {
    int t = blockIdx.x * blockDim.x + threadIdx.x;
    if (t < Bn*Nn) {
        float m = d_colmax[t];
        float Z = d_colZ[t] + (float)(Nn - d_colcnt[t]) * expf(-m);
        d_colinv[t] = 1.0f / Z;
    }
}

// ---------------- per-edge attention value (overwrite eval) ----------------
__global__ void k_attval() {
    const int i = blockIdx.x, b = blockIdx.y;
    const int row = b*Nn + i;
    const int cnt = d_rowcnt[row];
    for (int s = threadIdx.x; s < cnt; s += 128) {
        const int col = d_colidx[(size_t)row*CAP + s];
        const float e = d_eval[(size_t)row*CAP + s];
        d_eval[(size_t)row*CAP + s] = expf(e - d_colmax[b*Nn + col]) * d_colinv[b*Nn + col];
    }
}

// ---------------- hop: az = relu(att @ r), gated blend ----------------
__global__ void k_hop(int which, const float* __restrict__ gw, float* __restrict__ outbuf) {
    const float* rin  = (which == 0) ? d_h  : (which == 1 ? d_r1 : d_r2);
    float*       rout = (which == 0) ? d_r1 : (which == 1 ? d_r2 : outbuf);

    const int team = threadIdx.x >> 7;        // 2 teams of 128
    const int d    = threadIdx.x & 127;
    const int row  = blockIdx.x * 2 + team;
    const int b    = row >> 10;

    const float* rb = rin + (size_t)b * Nn * Dn;
    const int    cnt = d_rowcnt[row];
    const int*   ci  = d_colidx + (size_t)row * CAP;
    const float* ev  = d_eval   + (size_t)row * CAP;

    float acc = 0.0f;
    int s = 0;
    for (; s + 4 <= cnt; s += 4) {
        int   c0 = ci[s], c1 = ci[s+1], c2 = ci[s+2], c3 = ci[s+3];
        float v0 = ev[s], v1 = ev[s+1], v2 = ev[s+2], v3 = ev[s+3];
        acc += v0 * rb[c0*Dn + d];
        acc += v1 * rb[c1*Dn + d];
        acc += v2 * rb[c2*Dn + d];
        acc += v3 * rb[c3*Dn + d];
    }
    for (; s < cnt; ++s) acc += ev[s] * rb[ci[s]*Dn + d];

    const float az = fmaxf(acc, 0.0f);

    // gate: coeff = sigmoid(hdot[row] + az . gw[128:256])
    float p = az * gw[128 + d];
    #pragma unroll
    for (int off = 16; off; off >>= 1) p += __shfl_xor_sync(~0u, p, off);
    __shared__ float red[8];
    const int warp = threadIdx.x >> 5;
    if ((threadIdx.x & 31) == 0) red[warp] = p;
    __syncthreads();
    const float dot = red[team*4+0] + red[team*4+1] + red[team*4+2] + red[team*4+3];
    const float z = d_hdot[row] + dot;
    const float coeff = 1.0f / (1.0f + expf(-z));
    const float hv = d_h[(size_t)row*Dn + d];
    rout[(size_t)row*Dn + d] = coeff * hv + (1.0f - coeff) * az;
}

// ---------------- launch ----------------
extern "C" void kernel_launch(void* const* d_in, const int* in_sizes, int n_in,
                              void* d_out, int out_size) {
    const float* x   = (const float*)d_in[0];
    const float* adj = (const float*)d_in[1];
    const float* Ww  = (const float*)d_in[2];
    const float* Wb  = (const float*)d_in[3];
    const float* A   = (const float*)d_in[4];
    const float* gw  = (const float*)d_in[5];
    const float* gb  = (const float*)d_in[6];
    float* out = (float*)d_out;

    cudaFuncSetAttribute(k_hg, cudaFuncAttributeMaxDynamicSharedMemorySize, HG_SMEM);

    k_init<<<64, 256>>>();
    k_hg<<<(Bn*Nn)/HG_ROWS, 128, HG_SMEM>>>(x, Ww, Wb, A, gw, gb);
    k_build<<<dim3(Nn, Bn), 256>>>(adj);
    k_edgeE<<<dim3(Nn, Bn), 128>>>();
    k_edgeZ<<<dim3(Nn, Bn), 128>>>();
    k_colfinal<<<64, 256>>>();
    k_attval<<<dim3(Nn, Bn), 128>>>();
    k_hop<<<(Bn*Nn)/2, 256>>>(0, gw, out);
    k_hop<<<(Bn*Nn)/2, 256>>>(1, gw, out);
    k_hop<<<(Bn*Nn)/2, 256>>>(2, gw, out);
}

// round 2
// speedup vs baseline: 1.5419x; 1.5419x over previous
#include <cuda_runtime.h>
#include <math.h>

#define Bn   16
#define Nn   1024
#define Dn   128
#define CAP  256     // max edges per row (mean ~52)

// ---------------- scratch (static device globals; no allocation) ----------------
__device__ float d_h   [Bn*Nn*Dn];
__device__ float d_g   [Bn*Nn*Dn];
__device__ float d_hdot[Bn*Nn];
__device__ int   d_colidx[Bn*Nn*CAP];
__device__ float d_eval  [Bn*Nn*CAP];
__device__ int   d_rowcnt[Bn*Nn];
__device__ int   d_colcnt[Bn*Nn];
__device__ float d_colZ  [Bn*Nn];
__device__ float d_colinv[Bn*Nn];
__device__ float d_r1[Bn*Nn*Dn];
__device__ float d_r2[Bn*Nn*Dn];

// ---------------- init: zero column stats ----------------
__global__ void k_init() {
    int t = blockIdx.x * blockDim.x + threadIdx.x;
    if (t < Bn*Nn) { d_colcnt[t] = 0; d_colZ[t] = 0.0f; }
}

// ---------------- k_h: h = x W^T + b  (W cached once per block, padded smem) ----------------
#define HG_GRID  410          // 410*40 = 16400 >= 16384, 3 blocks/SM possible
#define HG_SMEM  ((128*132 + 8*128)*4)

__global__ void k_h(const float* __restrict__ x, const float* __restrict__ Ww,
                    const float* __restrict__ Wb) {
    extern __shared__ float sm[];
    float* Ws = sm;               // [128][132] W row-major, padded
    float* xs = sm + 128*132;     // 8 rows of x

    const int t = threadIdx.x;    // 128 threads
    for (int i = t; i < 128*128; i += 128)
        Ws[(i >> 7)*132 + (i & 127)] = Ww[i];
    const float bo = Wb[t];
    const int r0base = blockIdx.x * 40;

    for (int it = 0; it < 5; it++) {
        const int r0 = r0base + it*8;
        __syncthreads();
        #pragma unroll
        for (int q = 0; q < 2; q++) {
            int idx = t + q*128;              // 0..255
            int rr = idx >> 5, wi = idx & 31;
            int row = r0 + rr;
            float4 v = make_float4(0,0,0,0);
            if (row < Bn*Nn) v = *(const float4*)&x[(size_t)row*Dn + wi*4];
            *(float4*)&xs[rr*128 + wi*4] = v;
        }
        __syncthreads();

        float acc[8];
        #pragma unroll
        for (int r = 0; r < 8; r++) acc[r] = bo;
        #pragma unroll 4
        for (int d4 = 0; d4 < 32; d4++) {
            float4 w4 = *(float4*)&Ws[t*132 + d4*4];
            #pragma unroll
            for (int r = 0; r < 8; r++) {
                float4 x4 = *(float4*)&xs[r*128 + d4*4];
                acc[r] += x4.x*w4.x + x4.y*w4.y + x4.z*w4.z + x4.w*w4.w;
            }
        }
        #pragma unroll
        for (int r = 0; r < 8; r++) {
            int row = r0 + r;
            if (row < Bn*Nn) d_h[(size_t)row*Dn + t] = acc[r];
        }
    }
}

// ---------------- k_g: g = h A ; hdot = h.gw[0:128] + gb ----------------
__global__ void k_g(const float* __restrict__ Am, const float* __restrict__ gw,
                    const float* __restrict__ gb) {
    extern __shared__ float sm[];
    float* As = sm;               // [o][dd] = A[dd][o], padded 132
    float* hs = sm + 128*132;     // 8 rows of h

    const int t = threadIdx.x, lane = t & 31, warp = t >> 5;
    for (int i = t; i < 128*128; i += 128)
        As[(i & 127)*132 + (i >> 7)] = Am[i];
    const float4 gw4 = *(const float4*)&gw[lane*4];
    const float gb0 = gb[0];
    const int r0base = blockIdx.x * 40;

    for (int it = 0; it < 5; it++) {
        const int r0 = r0base + it*8;
        __syncthreads();
        #pragma unroll
        for (int q = 0; q < 2; q++) {
            int idx = t + q*128;
            int rr = idx >> 5, wi = idx & 31;
            int row = r0 + rr;
            float4 v = make_float4(0,0,0,0);
            if (row < Bn*Nn) v = *(const float4*)&d_h[(size_t)row*Dn + wi*4];
            *(float4*)&hs[rr*128 + wi*4] = v;
        }
        __syncthreads();

        float acc[8];
        #pragma unroll
        for (int r = 0; r < 8; r++) acc[r] = 0.0f;
        #pragma unroll 4
        for (int d4 = 0; d4 < 32; d4++) {
            float4 a4 = *(float4*)&As[t*132 + d4*4];
            #pragma unroll
            for (int r = 0; r < 8; r++) {
                float4 h4 = *(float4*)&hs[r*128 + d4*4];
                acc[r] += h4.x*a4.x + h4.y*a4.y + h4.z*a4.z + h4.w*a4.w;
            }
        }
        #pragma unroll
        for (int r = 0; r < 8; r++) {
            int row = r0 + r;
            if (row < Bn*Nn) d_g[(size_t)row*Dn + t] = acc[r];
        }

        // hdot: 4 warps x 2 rows each
        #pragma unroll
        for (int rr = 0; rr < 2; rr++) {
            int r = warp*2 + rr;
            int row = r0 + r;
            float4 h4 = *(float4*)&hs[r*128 + lane*4];
            float p = h4.x*gw4.x + h4.y*gw4.y + h4.z*gw4.z + h4.w*gw4.w;
            #pragma unroll
            for (int off = 16; off; off >>= 1) p += __shfl_xor_sync(~0u, p, off);
            if (lane == 0 && row < Bn*Nn) d_hdot[row] = p + gb0;
        }
    }
}

// ---------------- fused: build row CSR + edge score + exp + column Z ----------------
__global__ void k_buildE(const float* __restrict__ adj) {
    const int i = blockIdx.x, b = blockIdx.y;
    const int row = b*Nn + i;
    __shared__ int   cols[CAP];
    __shared__ float P[256];      // g_i | h_i
    __shared__ int   cnt;
    const int t = threadIdx.x, lane = t & 31, warp = t >> 5;
    if (t == 0) cnt = 0;
    P[t]       = d_g[(size_t)row*Dn + t];
    P[128 + t] = d_h[(size_t)row*Dn + t];
    __syncthreads();

    const float4* a4 = (const float4*)(adj + (size_t)row * Nn);
    #pragma unroll
    for (int q = 0; q < 2; q++) {
        int idx = t + q*128;          // float4 index 0..255
        float4 v = a4[idx];
        if (v.x > 0.0f) { int s = atomicAdd(&cnt,1); if (s < CAP) cols[s] = idx*4+0; atomicAdd(&d_colcnt[b*Nn + idx*4+0], 1); }
        if (v.y > 0.0f) { int s = atomicAdd(&cnt,1); if (s < CAP) cols[s] = idx*4+1; atomicAdd(&d_colcnt[b*Nn + idx*4+1], 1); }
        if (v.z > 0.0f) { int s = atomicAdd(&cnt,1); if (s < CAP) cols[s] = idx*4+2; atomicAdd(&d_colcnt[b*Nn + idx*4+2], 1); }
        if (v.w > 0.0f) { int s = atomicAdd(&cnt,1); if (s < CAP) cols[s] = idx*4+3; atomicAdd(&d_colcnt[b*Nn + idx*4+3], 1); }
    }
    __syncthreads();
    const int n = (cnt < CAP) ? cnt : CAP;
    if (t == 0) d_rowcnt[row] = n;
    for (int s = t; s < n; s += 128) d_colidx[(size_t)row*CAP + s] = cols[s];

    // hoist this row's g/h slice into registers: 8 lanes per edge, 16 floats/lane
    const int lo = lane & 7, grp = lane >> 3;
    float4 rg[4], rh[4];
    #pragma unroll
    for (int k = 0; k < 4; k++) {
        rg[k] = *(float4*)&P[lo*16 + k*4];
        rh[k] = *(float4*)&P[128 + lo*16 + k*4];
    }

    // 4 warps x 4 edge-groups => 16 edges in flight per block
    for (int s0 = warp*4; s0 < n; s0 += 16) {
        const int s = s0 + grp;
        const int c = cols[(s < n) ? s : s0];
        const float* hb = &d_h[((size_t)b*Nn + c)*Dn + lo*16];
        const float* gc_ = &d_g[((size_t)b*Nn + c)*Dn + lo*16];
        float p = 0.0f;
        #pragma unroll
        for (int k = 0; k < 4; k++) {
            float4 hc = *(const float4*)&hb[k*4];
            float4 gc = *(const float4*)&gc_[k*4];
            p += rg[k].x*hc.x + rg[k].y*hc.y + rg[k].z*hc.z + rg[k].w*hc.w;
            p += rh[k].x*gc.x + rh[k].y*gc.y + rh[k].z*gc.z + rh[k].w*gc.w;
        }
        p += __shfl_xor_sync(~0u, p, 1);
        p += __shfl_xor_sync(~0u, p, 2);
        p += __shfl_xor_sync(~0u, p, 4);
        if (lo == 0 && s < n) {
            float ev = __expf(p);                         // no max-shift needed: |e| <~ 10
            d_eval[(size_t)row*CAP + s] = ev;
            atomicAdd(&d_colZ[b*Nn + c], ev);
        }
    }
}

// ---------------- finalize: colinv = 1 / (Z_edges + (N - cnt)*exp(0)) ----------------
__global__ void k_colfinal() {
    int t = blockIdx.x * blockDim.x + threadIdx.x;
    if (t < Bn*Nn)
        d_colinv[t] = 1.0f / (d_colZ[t] + (float)(Nn - d_colcnt[t]));
}

// ---------------- hop: warp per row, float4 lanes; hop0 normalizes in place ----------------
__global__ void k_hop(int which, const float* __restrict__ gw, float* __restrict__ outbuf,
                      int norm) {
    const float* rin  = (which == 0) ? d_h  : (which == 1 ? d_r1 : d_r2);
    float*       rout = (which == 0) ? d_r1 : (which == 1 ? d_r2 : outbuf);

    const int lane = threadIdx.x & 31, warp = threadIdx.x >> 5;
    const int row  = blockIdx.x * 8 + warp;
    const int b    = row >> 10;

    const float* rb  = rin + (size_t)b * Nn * Dn;
    const int    cnt = d_rowcnt[row];
    const int*   ci  = d_colidx + (size_t)row * CAP;
    float*       ev  = d_eval   + (size_t)row * CAP;

    float4 acc = make_float4(0,0,0,0);
    int s = 0;
    for (; s + 4 <= cnt; s += 4) {
        int   c0 = ci[s], c1 = ci[s+1], c2 = ci[s+2], c3 = ci[s+3];
        float v0 = ev[s], v1 = ev[s+1], v2 = ev[s+2], v3 = ev[s+3];
        if (norm) {
            v0 *= d_colinv[b*Nn + c0]; v1 *= d_colinv[b*Nn + c1];
            v2 *= d_colinv[b*Nn + c2]; v3 *= d_colinv[b*Nn + c3];
            if (lane == 0) { ev[s] = v0; ev[s+1] = v1; ev[s+2] = v2; ev[s+3] = v3; }
        }
        float4 r0 = *(const float4*)&rb[(size_t)c0*Dn + lane*4];
        float4 r1 = *(const float4*)&rb[(size_t)c1*Dn + lane*4];
        float4 r2 = *(const float4*)&rb[(size_t)c2*Dn + lane*4];
        float4 r3 = *(const float4*)&rb[(size_t)c3*Dn + lane*4];
        acc.x += v0*r0.x + v1*r1.x + v2*r2.x + v3*r3.x;
        acc.y += v0*r0.y + v1*r1.y + v2*r2.y + v3*r3.y;
        acc.z += v0*r0.z + v1*r1.z + v2*r2.z + v3*r3.z;
        acc.w += v0*r0.w + v1*r1.w + v2*r2.w + v3*r3.w;
    }
    for (; s < cnt; ++s) {
        int c = ci[s];
        float v = ev[s];
        if (norm) {
            v *= d_colinv[b*Nn + c];
            if (lane == 0) ev[s] = v;
        }
        float4 r0 = *(const float4*)&rb[(size_t)c*Dn + lane*4];
        acc.x += v*r0.x; acc.y += v*r0.y; acc.z += v*r0.z; acc.w += v*r0.w;
    }

    float4 az = make_float4(fmaxf(acc.x,0.f), fmaxf(acc.y,0.f),
                            fmaxf(acc.z,0.f), fmaxf(acc.w,0.f));

    // gate
    float4 gw4 = *(const float4*)&gw[128 + lane*4];
    float p = az.x*gw4.x + az.y*gw4.y + az.z*gw4.z + az.w*gw4.w;
    #pragma unroll
    for (int off = 16; off; off >>= 1) p += __shfl_xor_sync(~0u, p, off);
    const float zv = d_hdot[row] + p;
    const float coeff = 1.0f / (1.0f + __expf(-zv));
    const float om = 1.0f - coeff;
    float4 h4 = *(const float4*)&d_h[(size_t)row*Dn + lane*4];
    float4 o4;
    o4.x = coeff*h4.x + om*az.x;
    o4.y = coeff*h4.y + om*az.y;
    o4.z = coeff*h4.z + om*az.z;
    o4.w = coeff*h4.w + om*az.w;
    *(float4*)&rout[(size_t)row*Dn + lane*4] = o4;
}

// ---------------- launch ----------------
extern "C" void kernel_launch(void* const* d_in, const int* in_sizes, int n_in,
                              void* d_out, int out_size) {
    const float* x   = (const float*)d_in[0];
    const float* adj = (const float*)d_in[1];
    const float* Ww  = (const float*)d_in[2];
    const float* Wb  = (const float*)d_in[3];
    const float* A   = (const float*)d_in[4];
    const float* gw  = (const float*)d_in[5];
    const float* gb  = (const float*)d_in[6];
    float* out = (float*)d_out;

    cudaFuncSetAttribute(k_h, cudaFuncAttributeMaxDynamicSharedMemorySize, HG_SMEM);
    cudaFuncSetAttribute(k_g, cudaFuncAttributeMaxDynamicSharedMemorySize, HG_SMEM);

    k_init<<<64, 256>>>();
    k_h<<<HG_GRID, 128, HG_SMEM>>>(x, Ww, Wb);
    k_g<<<HG_GRID, 128, HG_SMEM>>>(A, gw, gb);
    k_buildE<<<dim3(Nn, Bn), 128>>>(adj);
    k_colfinal<<<64, 256>>>();
    k_hop<<<2048, 256>>>(0, gw, out, 1);
    k_hop<<<2048, 256>>>(1, gw, out, 0);
    k_hop<<<2048, 256>>>(2, gw, out, 0);
}

// round 3
// speedup vs baseline: 1.9320x; 1.2530x over previous
#include <cuda_runtime.h>
#include <math.h>

#define Bn   16
#define Nn   1024
#define Dn   128
#define CAP  256     // max edges per row (mean ~52)

// ---------------- scratch (static device globals; no allocation) ----------------
__device__ float d_h   [Bn*Nn*Dn];
__device__ float d_g   [Bn*Nn*Dn];
__device__ float d_hdot[Bn*Nn];
__device__ int   d_colidx[Bn*Nn*CAP];
__device__ float d_eval  [Bn*Nn*CAP];
__device__ int   d_rowcnt[Bn*Nn];
__device__ float d_colZ  [Bn*Nn];
__device__ float d_colinv[Bn*Nn];
__device__ float d_r1[Bn*Nn*Dn];
__device__ float d_r2[Bn*Nn*Dn];

// ---------------- init: colZ starts at N (every column contributes exp(0) per non-edge,
// and edges add (exp(e)-1) so the count correction is implicit) ----------------
__global__ void k_init() {
    int t = blockIdx.x * blockDim.x + threadIdx.x;
    if (t < Bn*Nn) d_colZ[t] = (float)Nn;
}

// ---------------- k_h: h = x W^T + b  (W cached once per block, padded smem) ----------------
#define HG_GRID  410          // 410*40 = 16400 >= 16384
#define HG_SMEM  ((128*132 + 8*128)*4)

__global__ void k_h(const float* __restrict__ x, const float* __restrict__ Ww,
                    const float* __restrict__ Wb) {
    extern __shared__ float sm[];
    float* Ws = sm;               // [128][132] W row-major, padded
    float* xs = sm + 128*132;     // 8 rows of x

    const int t = threadIdx.x;    // 128 threads
    for (int i = t; i < 128*128; i += 128)
        Ws[(i >> 7)*132 + (i & 127)] = Ww[i];
    const float bo = Wb[t];
    const int r0base = blockIdx.x * 40;

    for (int it = 0; it < 5; it++) {
        const int r0 = r0base + it*8;
        __syncthreads();
        #pragma unroll
        for (int q = 0; q < 2; q++) {
            int idx = t + q*128;              // 0..255
            int rr = idx >> 5, wi = idx & 31;
            int row = r0 + rr;
            float4 v = make_float4(0,0,0,0);
            if (row < Bn*Nn) v = *(const float4*)&x[(size_t)row*Dn + wi*4];
            *(float4*)&xs[rr*128 + wi*4] = v;
        }
        __syncthreads();

        float acc[8];
        #pragma unroll
        for (int r = 0; r < 8; r++) acc[r] = bo;
        #pragma unroll 4
        for (int d4 = 0; d4 < 32; d4++) {
            float4 w4 = *(float4*)&Ws[t*132 + d4*4];
            #pragma unroll
            for (int r = 0; r < 8; r++) {
                float4 x4 = *(float4*)&xs[r*128 + d4*4];
                acc[r] += x4.x*w4.x + x4.y*w4.y + x4.z*w4.z + x4.w*w4.w;
            }
        }
        #pragma unroll
        for (int r = 0; r < 8; r++) {
            int row = r0 + r;
            if (row < Bn*Nn) d_h[(size_t)row*Dn + t] = acc[r];
        }
    }
}

// ---------------- k_g: g = h A ; hdot = h.gw[0:128] + gb ----------------
__global__ void k_g(const float* __restrict__ Am, const float* __restrict__ gw,
                    const float* __restrict__ gb) {
    extern __shared__ float sm[];
    float* As = sm;               // [o][dd] = A[dd][o], padded 132
    float* hs = sm + 128*132;     // 8 rows of h

    const int t = threadIdx.x, lane = t & 31, warp = t >> 5;
    for (int i = t; i < 128*128; i += 128)
        As[(i & 127)*132 + (i >> 7)] = Am[i];
    const float4 gw4 = *(const float4*)&gw[lane*4];
    const float gb0 = gb[0];
    const int r0base = blockIdx.x * 40;

    for (int it = 0; it < 5; it++) {
        const int r0 = r0base + it*8;
        __syncthreads();
        #pragma unroll
        for (int q = 0; q < 2; q++) {
            int idx = t + q*128;
            int rr = idx >> 5, wi = idx & 31;
            int row = r0 + rr;
            float4 v = make_float4(0,0,0,0);
            if (row < Bn*Nn) v = *(const float4*)&d_h[(size_t)row*Dn + wi*4];
            *(float4*)&hs[rr*128 + wi*4] = v;
        }
        __syncthreads();

        float acc[8];
        #pragma unroll
        for (int r = 0; r < 8; r++) acc[r] = 0.0f;
        #pragma unroll 4
        for (int d4 = 0; d4 < 32; d4++) {
            float4 a4 = *(float4*)&As[t*132 + d4*4];
            #pragma unroll
            for (int r = 0; r < 8; r++) {
                float4 h4 = *(float4*)&hs[r*128 + d4*4];
                acc[r] += h4.x*a4.x + h4.y*a4.y + h4.z*a4.z + h4.w*a4.w;
            }
        }
        #pragma unroll
        for (int r = 0; r < 8; r++) {
            int row = r0 + r;
            if (row < Bn*Nn) d_g[(size_t)row*Dn + t] = acc[r];
        }

        // hdot: 4 warps x 2 rows each
        #pragma unroll
        for (int rr = 0; rr < 2; rr++) {
            int r = warp*2 + rr;
            int row = r0 + r;
            float4 h4 = *(float4*)&hs[r*128 + lane*4];
            float p = h4.x*gw4.x + h4.y*gw4.y + h4.z*gw4.z + h4.w*gw4.w;
            #pragma unroll
            for (int off = 16; off; off >>= 1) p += __shfl_xor_sync(~0u, p, off);
            if (lane == 0 && row < Bn*Nn) d_hdot[row] = p + gb0;
        }
    }
}

// ---------------- fused: build row CSR (ballot-aggregated) + edge score + exp + column Z ----------------
__global__ void k_buildE(const float* __restrict__ adj) {
    const int i = blockIdx.x, b = blockIdx.y;
    const int row = b*Nn + i;
    __shared__ int   cols[CAP];
    __shared__ float P[256];      // g_i | h_i
    __shared__ int   cnt;
    const int t = threadIdx.x, lane = t & 31, warp = t >> 5;
    if (t == 0) cnt = 0;
    P[t]       = d_g[(size_t)row*Dn + t];
    P[128 + t] = d_h[(size_t)row*Dn + t];
    __syncthreads();

    // warp-aggregated CSR build: 1 shared atomic per warp per component pass
    const unsigned ltmask = (1u << lane) - 1u;
    const float4* a4 = (const float4*)(adj + (size_t)row * Nn);
    #pragma unroll
    for (int q = 0; q < 2; q++) {
        int idx = t + q*128;          // float4 index 0..255
        float4 v = a4[idx];
        #pragma unroll
        for (int c = 0; c < 4; c++) {
            float val = (c == 0) ? v.x : (c == 1) ? v.y : (c == 2) ? v.z : v.w;
            bool hit = val > 0.0f;
            unsigned m = __ballot_sync(~0u, hit);
            int base = 0;
            if (lane == 0 && m) base = atomicAdd(&cnt, __popc(m));
            base = __shfl_sync(~0u, base, 0);
            if (hit) {
                int s = base + __popc(m & ltmask);
                if (s < CAP) cols[s] = idx*4 + c;
            }
        }
    }
    __syncthreads();
    const int n = (cnt < CAP) ? cnt : CAP;
    if (t == 0) d_rowcnt[row] = n;
    for (int s = t; s < n; s += 128) d_colidx[(size_t)row*CAP + s] = cols[s];

    // hoist this row's g/h slice into registers, COALESCED layout:
    // lane 'lo' owns float4 at [lo*4 + k*32] -> per k the 8-lane group covers one 128B line
    const int lo = lane & 7, grp = lane >> 3;
    float4 rg[4], rh[4];
    #pragma unroll
    for (int k = 0; k < 4; k++) {
        rg[k] = *(float4*)&P[k*32 + lo*4];
        rh[k] = *(float4*)&P[128 + k*32 + lo*4];
    }

    // 4 warps x 4 edge-groups => 16 edges in flight per block
    for (int s0 = warp*4; s0 < n; s0 += 16) {
        const int s = s0 + grp;
        const int c = cols[(s < n) ? s : s0];
        const float* hb = &d_h[((size_t)b*Nn + c)*Dn];
        const float* gb_ = &d_g[((size_t)b*Nn + c)*Dn];
        float4 hc[4], gc[4];
        #pragma unroll
        for (int k = 0; k < 4; k++) {
            hc[k] = *(const float4*)&hb[k*32 + lo*4];
            gc[k] = *(const float4*)&gb_[k*32 + lo*4];
        }
        float p = 0.0f;
        #pragma unroll
        for (int k = 0; k < 4; k++) {
            p += rg[k].x*hc[k].x + rg[k].y*hc[k].y + rg[k].z*hc[k].z + rg[k].w*hc[k].w;
            p += rh[k].x*gc[k].x + rh[k].y*gc[k].y + rh[k].z*gc[k].z + rh[k].w*gc[k].w;
        }
        p += __shfl_xor_sync(~0u, p, 1);
        p += __shfl_xor_sync(~0u, p, 2);
        p += __shfl_xor_sync(~0u, p, 4);
        if (lo == 0 && s < n) {
            float ev = __expf(p);                         // |e| small: no max-shift needed
            d_eval[(size_t)row*CAP + s] = ev;
            atomicAdd(&d_colZ[b*Nn + c], ev - 1.0f);      // colZ pre-seeded with N
        }
    }
}

// ---------------- finalize: colinv = 1 / Z ----------------
__global__ void k_colfinal() {
    int t = blockIdx.x * blockDim.x + threadIdx.x;
    if (t < Bn*Nn)
        d_colinv[t] = 1.0f / d_colZ[t];
}

// ---------------- hop: warp per row, float4 lanes; hop0 normalizes in place ----------------
__global__ void k_hop(int which, const float* __restrict__ gw, float* __restrict__ outbuf,
                      int norm) {
    const float* rin  = (which == 0) ? d_h  : (which == 1 ? d_r1 : d_r2);
    float*       rout = (which == 0) ? d_r1 : (which == 1 ? d_r2 : outbuf);

    const int lane = threadIdx.x & 31, warp = threadIdx.x >> 5;
    const int row  = blockIdx.x * 8 + warp;
    const int b    = row >> 10;

    const float* rb  = rin + (size_t)b * Nn * Dn;
    const int    cnt = d_rowcnt[row];
    const int*   ci  = d_colidx + (size_t)row * CAP;
    float*       ev  = d_eval   + (size_t)row * CAP;

    float4 acc = make_float4(0,0,0,0);
    int s = 0;
    for (; s + 4 <= cnt; s += 4) {
        int   c0 = ci[s], c1 = ci[s+1], c2 = ci[s+2], c3 = ci[s+3];
        float v0 = ev[s], v1 = ev[s+1], v2 = ev[s+2], v3 = ev[s+3];
        if (norm) {
            v0 *= d_colinv[b*Nn + c0]; v1 *= d_colinv[b*Nn + c1];
            v2 *= d_colinv[b*Nn + c2]; v3 *= d_colinv[b*Nn + c3];
            if (lane == 0) { ev[s] = v0; ev[s+1] = v1; ev[s+2] = v2; ev[s+3] = v3; }
        }
        float4 r0 = *(const float4*)&rb[(size_t)c0*Dn + lane*4];
        float4 r1 = *(const float4*)&rb[(size_t)c1*Dn + lane*4];
        float4 r2 = *(const float4*)&rb[(size_t)c2*Dn + lane*4];
        float4 r3 = *(const float4*)&rb[(size_t)c3*Dn + lane*4];
        acc.x += v0*r0.x + v1*r1.x + v2*r2.x + v3*r3.x;
        acc.y += v0*r0.y + v1*r1.y + v2*r2.y + v3*r3.y;
        acc.z += v0*r0.z + v1*r1.z + v2*r2.z + v3*r3.z;
        acc.w += v0*r0.w + v1*r1.w + v2*r2.w + v3*r3.w;
    }
    for (; s < cnt; ++s) {
        int c = ci[s];
        float v = ev[s];
        if (norm) {
            v *= d_colinv[b*Nn + c];
            if (lane == 0) ev[s] = v;
        }
        float4 r0 = *(const float4*)&rb[(size_t)c*Dn + lane*4];
        acc.x += v*r0.x; acc.y += v*r0.y; acc.z += v*r0.z; acc.w += v*r0.w;
    }

    float4 az = make_float4(fmaxf(acc.x,0.f), fmaxf(acc.y,0.f),
                            fmaxf(acc.z,0.f), fmaxf(acc.w,0.f));

    // gate
    float4 gw4 = *(const float4*)&gw[128 + lane*4];
    float p = az.x*gw4.x + az.y*gw4.y + az.z*gw4.z + az.w*gw4.w;
    #pragma unroll
    for (int off = 16; off; off >>= 1) p += __shfl_xor_sync(~0u, p, off);
    const float zv = d_hdot[row] + p;
    const float coeff = 1.0f / (1.0f + __expf(-zv));
    const float om = 1.0f - coeff;
    float4 h4 = *(const float4*)&d_h[(size_t)row*Dn + lane*4];
    float4 o4;
    o4.x = coeff*h4.x + om*az.x;
    o4.y = coeff*h4.y + om*az.y;
    o4.z = coeff*h4.z + om*az.z;
    o4.w = coeff*h4.w + om*az.w;
    *(float4*)&rout[(size_t)row*Dn + lane*4] = o4;
}

// ---------------- launch ----------------
extern "C" void kernel_launch(void* const* d_in, const int* in_sizes, int n_in,
                              void* d_out, int out_size) {
    const float* x   = (const float*)d_in[0];
    const float* adj = (const float*)d_in[1];
    const float* Ww  = (const float*)d_in[2];
    const float* Wb  = (const float*)d_in[3];
    const float* A   = (const float*)d_in[4];
    const float* gw  = (const float*)d_in[5];
    const float* gb  = (const float*)d_in[6];
    float* out = (float*)d_out;

    cudaFuncSetAttribute(k_h, cudaFuncAttributeMaxDynamicSharedMemorySize, HG_SMEM);
    cudaFuncSetAttribute(k_g, cudaFuncAttributeMaxDynamicSharedMemorySize, HG_SMEM);

    k_init<<<64, 256>>>();
    k_h<<<HG_GRID, 128, HG_SMEM>>>(x, Ww, Wb);
    k_g<<<HG_GRID, 128, HG_SMEM>>>(A, gw, gb);
    k_buildE<<<dim3(Nn, Bn), 128>>>(adj);
    k_colfinal<<<64, 256>>>();
    k_hop<<<2048, 256>>>(0, gw, out, 1);
    k_hop<<<2048, 256>>>(1, gw, out, 0);
    k_hop<<<2048, 256>>>(2, gw, out, 0);
}

// round 4
// speedup vs baseline: 1.9626x; 1.0159x over previous
#include <cuda_runtime.h>
#include <math.h>

#define Bn   16
#define Nn   1024
#define Dn   128
#define CAP  256     // max edges per row (mean ~52)

// ---------------- scratch (static device globals; no allocation) ----------------
__device__ float d_h   [Bn*Nn*Dn];
__device__ float d_g   [Bn*Nn*Dn];     // g' = h (A + A^T)
__device__ float d_hdot[Bn*Nn];
__device__ int   d_colidx[Bn*Nn*CAP];
__device__ float d_eval  [Bn*Nn*CAP];
__device__ int   d_rowcnt[Bn*Nn];
__device__ float d_colZ  [Bn*Nn];
__device__ float d_colinv[Bn*Nn];
__device__ float d_r1[Bn*Nn*Dn];
__device__ float d_r2[Bn*Nn*Dn];

// ---------------- init: colZ starts at N (non-edges contribute exp(0)=1 each;
// edges add (exp(e)-1)) ----------------
__global__ void k_init() {
    int t = blockIdx.x * blockDim.x + threadIdx.x;
    if (t < Bn*Nn) d_colZ[t] = (float)Nn;
}

// ---------------- k_h: h = x W^T + b ----------------
#define HG_GRID  410          // 410*40 = 16400 >= 16384
#define HG_SMEM  ((128*132 + 8*128)*4)

__global__ void k_h(const float* __restrict__ x, const float* __restrict__ Ww,
                    const float* __restrict__ Wb) {
    extern __shared__ float sm[];
    float* Ws = sm;               // [128][132] W row-major, padded
    float* xs = sm + 128*132;     // 8 rows of x

    const int t = threadIdx.x;    // 128 threads
    for (int i = t; i < 128*128; i += 128)
        Ws[(i >> 7)*132 + (i & 127)] = Ww[i];
    const float bo = Wb[t];
    const int r0base = blockIdx.x * 40;

    for (int it = 0; it < 5; it++) {
        const int r0 = r0base + it*8;
        __syncthreads();
        #pragma unroll
        for (int q = 0; q < 2; q++) {
            int idx = t + q*128;              // 0..255
            int rr = idx >> 5, wi = idx & 31;
            int row = r0 + rr;
            float4 v = make_float4(0,0,0,0);
            if (row < Bn*Nn) v = *(const float4*)&x[(size_t)row*Dn + wi*4];
            *(float4*)&xs[rr*128 + wi*4] = v;
        }
        __syncthreads();

        float acc[8];
        #pragma unroll
        for (int r = 0; r < 8; r++) acc[r] = bo;
        #pragma unroll 4
        for (int d4 = 0; d4 < 32; d4++) {
            float4 w4 = *(float4*)&Ws[t*132 + d4*4];
            #pragma unroll
            for (int r = 0; r < 8; r++) {
                float4 x4 = *(float4*)&xs[r*128 + d4*4];
                acc[r] += x4.x*w4.x + x4.y*w4.y + x4.z*w4.z + x4.w*w4.w;
            }
        }
        #pragma unroll
        for (int r = 0; r < 8; r++) {
            int row = r0 + r;
            if (row < Bn*Nn) d_h[(size_t)row*Dn + t] = acc[r];
        }
    }
}

// ---------------- k_g: g' = h (A + A^T) ; hdot = h.gw[0:128] + gb ----------------
__global__ void k_g(const float* __restrict__ Am, const float* __restrict__ gw,
                    const float* __restrict__ gb) {
    extern __shared__ float sm[];
    float* As = sm;               // As[o][dd] = A[dd][o] + A[o][dd], padded 132
    float* hs = sm + 128*132;     // 8 rows of h

    const int t = threadIdx.x, lane = t & 31, warp = t >> 5;
    for (int i = t; i < 128*128; i += 128) {
        int dd = i >> 7, o = i & 127;
        As[o*132 + dd] = Am[i] + Am[o*128 + dd];   // A[dd][o] + A[o][dd]
    }
    const float4 gw4 = *(const float4*)&gw[lane*4];
    const float gb0 = gb[0];
    const int r0base = blockIdx.x * 40;

    for (int it = 0; it < 5; it++) {
        const int r0 = r0base + it*8;
        __syncthreads();
        #pragma unroll
        for (int q = 0; q < 2; q++) {
            int idx = t + q*128;
            int rr = idx >> 5, wi = idx & 31;
            int row = r0 + rr;
            float4 v = make_float4(0,0,0,0);
            if (row < Bn*Nn) v = *(const float4*)&d_h[(size_t)row*Dn + wi*4];
            *(float4*)&hs[rr*128 + wi*4] = v;
        }
        __syncthreads();

        float acc[8];
        #pragma unroll
        for (int r = 0; r < 8; r++) acc[r] = 0.0f;
        #pragma unroll 4
        for (int d4 = 0; d4 < 32; d4++) {
            float4 a4 = *(float4*)&As[t*132 + d4*4];
            #pragma unroll
            for (int r = 0; r < 8; r++) {
                float4 h4 = *(float4*)&hs[r*128 + d4*4];
                acc[r] += h4.x*a4.x + h4.y*a4.y + h4.z*a4.z + h4.w*a4.w;
            }
        }
        #pragma unroll
        for (int r = 0; r < 8; r++) {
            int row = r0 + r;
            if (row < Bn*Nn) d_g[(size_t)row*Dn + t] = acc[r];
        }

        // hdot: 4 warps x 2 rows each
        #pragma unroll
        for (int rr = 0; rr < 2; rr++) {
            int r = warp*2 + rr;
            int row = r0 + r;
            float4 h4 = *(float4*)&hs[r*128 + lane*4];
            float p = h4.x*gw4.x + h4.y*gw4.y + h4.z*gw4.z + h4.w*gw4.w;
            #pragma unroll
            for (int off = 16; off; off >>= 1) p += __shfl_xor_sync(~0u, p, off);
            if (lane == 0 && row < Bn*Nn) d_hdot[row] = p + gb0;
        }
    }
}

// ---------------- fused: build row CSR + edge score (g'_row . h_col) + exp + column Z ----------------
__global__ void k_buildE(const float* __restrict__ adj) {
    const int i = blockIdx.x, b = blockIdx.y;
    const int row = b*Nn + i;
    __shared__ int   cols[CAP];
    __shared__ float P[128];      // g'_row
    __shared__ int   cnt;
    const int t = threadIdx.x, lane = t & 31, warp = t >> 5;
    if (t == 0) cnt = 0;
    P[t] = d_g[(size_t)row*Dn + t];
    __syncthreads();

    // warp-aggregated CSR build
    const unsigned ltmask = (1u << lane) - 1u;
    const float4* a4 = (const float4*)(adj + (size_t)row * Nn);
    #pragma unroll
    for (int q = 0; q < 2; q++) {
        int idx = t + q*128;          // float4 index 0..255
        float4 v = a4[idx];
        #pragma unroll
        for (int c = 0; c < 4; c++) {
            float val = (c == 0) ? v.x : (c == 1) ? v.y : (c == 2) ? v.z : v.w;
            bool hit = val > 0.0f;
            unsigned m = __ballot_sync(~0u, hit);
            int base = 0;
            if (lane == 0 && m) base = atomicAdd(&cnt, __popc(m));
            base = __shfl_sync(~0u, base, 0);
            if (hit) {
                int s = base + __popc(m & ltmask);
                if (s < CAP) cols[s] = idx*4 + c;
            }
        }
    }
    __syncthreads();
    const int n = (cnt < CAP) ? cnt : CAP;
    if (t == 0) d_rowcnt[row] = n;
    for (int s = t; s < n; s += 128) d_colidx[(size_t)row*CAP + s] = cols[s];

    // g'_row slice in registers: lane group of 8, per k one full 128B line
    const int lo = lane & 7, grp = lane >> 3;
    float4 rg[4];
    #pragma unroll
    for (int k = 0; k < 4; k++) rg[k] = *(float4*)&P[k*32 + lo*4];

    // 4 warps x 4 groups x 2-edge unroll = 32 edges in flight per block
    for (int s0 = warp*4; s0 < n; s0 += 32) {
        const int sA = s0 + grp;
        const int sB = s0 + grp + 16;
        const int cA = cols[(sA < n) ? sA : 0];
        const int cB = cols[(sB < n) ? sB : 0];
        const float* hA = &d_h[((size_t)b*Nn + cA)*Dn];
        const float* hB = &d_h[((size_t)b*Nn + cB)*Dn];
        float4 a[4], bb[4];
        #pragma unroll
        for (int k = 0; k < 4; k++) {
            a[k]  = *(const float4*)&hA[k*32 + lo*4];
            bb[k] = *(const float4*)&hB[k*32 + lo*4];
        }
        float pA = 0.0f, pB = 0.0f;
        #pragma unroll
        for (int k = 0; k < 4; k++) {
            pA += rg[k].x*a[k].x  + rg[k].y*a[k].y  + rg[k].z*a[k].z  + rg[k].w*a[k].w;
            pB += rg[k].x*bb[k].x + rg[k].y*bb[k].y + rg[k].z*bb[k].z + rg[k].w*bb[k].w;
        }
        pA += __shfl_xor_sync(~0u, pA, 1); pB += __shfl_xor_sync(~0u, pB, 1);
        pA += __shfl_xor_sync(~0u, pA, 2); pB += __shfl_xor_sync(~0u, pB, 2);
        pA += __shfl_xor_sync(~0u, pA, 4); pB += __shfl_xor_sync(~0u, pB, 4);
        if (lo == 0) {
            if (sA < n) {
                float ev = __expf(pA);
                d_eval[(size_t)row*CAP + sA] = ev;
                atomicAdd(&d_colZ[b*Nn + cA], ev - 1.0f);
            }
            if (sB < n) {
                float ev = __expf(pB);
                d_eval[(size_t)row*CAP + sB] = ev;
                atomicAdd(&d_colZ[b*Nn + cB], ev - 1.0f);
            }
        }
    }
}

// ---------------- finalize: colinv = 1 / Z ----------------
__global__ void k_colfinal() {
    int t = blockIdx.x * blockDim.x + threadIdx.x;
    if (t < Bn*Nn)
        d_colinv[t] = 1.0f / d_colZ[t];
}

// ---------------- hop: warp per row, float4 lanes; hop0 normalizes in place ----------------
__global__ void k_hop(int which, const float* __restrict__ gw, float* __restrict__ outbuf,
                      int norm) {
    const float* rin  = (which == 0) ? d_h  : (which == 1 ? d_r1 : d_r2);
    float*       rout = (which == 0) ? d_r1 : (which == 1 ? d_r2 : outbuf);

    const int lane = threadIdx.x & 31, warp = threadIdx.x >> 5;
    const int row  = blockIdx.x * 8 + warp;
    const int b    = row >> 10;

    const float* rb  = rin + (size_t)b * Nn * Dn;
    const int    cnt = d_rowcnt[row];
    const int*   ci  = d_colidx + (size_t)row * CAP;
    float*       ev  = d_eval   + (size_t)row * CAP;

    float4 acc = make_float4(0,0,0,0);
    int s = 0;
    for (; s + 4 <= cnt; s += 4) {
        int   c0 = ci[s], c1 = ci[s+1], c2 = ci[s+2], c3 = ci[s+3];
        float v0 = ev[s], v1 = ev[s+1], v2 = ev[s+2], v3 = ev[s+3];
        if (norm) {
            v0 *= d_colinv[b*Nn + c0]; v1 *= d_colinv[b*Nn + c1];
            v2 *= d_colinv[b*Nn + c2]; v3 *= d_colinv[b*Nn + c3];
            if (lane == 0) { ev[s] = v0; ev[s+1] = v1; ev[s+2] = v2; ev[s+3] = v3; }
        }
        float4 r0 = *(const float4*)&rb[(size_t)c0*Dn + lane*4];
        float4 r1 = *(const float4*)&rb[(size_t)c1*Dn + lane*4];
        float4 r2 = *(const float4*)&rb[(size_t)c2*Dn + lane*4];
        float4 r3 = *(const float4*)&rb[(size_t)c3*Dn + lane*4];
        acc.x += v0*r0.x + v1*r1.x + v2*r2.x + v3*r3.x;
        acc.y += v0*r0.y + v1*r1.y + v2*r2.y + v3*r3.y;
        acc.z += v0*r0.z + v1*r1.z + v2*r2.z + v3*r3.z;
        acc.w += v0*r0.w + v1*r1.w + v2*r2.w + v3*r3.w;
    }
    for (; s < cnt; ++s) {
        int c = ci[s];
        float v = ev[s];
        if (norm) {
            v *= d_colinv[b*Nn + c];
            if (lane == 0) ev[s] = v;
        }
        float4 r0 = *(const float4*)&rb[(size_t)c*Dn + lane*4];
        acc.x += v*r0.x; acc.y += v*r0.y; acc.z += v*r0.z; acc.w += v*r0.w;
    }

    float4 az = make_float4(fmaxf(acc.x,0.f), fmaxf(acc.y,0.f),
                            fmaxf(acc.z,0.f), fmaxf(acc.w,0.f));

    // gate
    float4 gw4 = *(const float4*)&gw[128 + lane*4];
    float p = az.x*gw4.x + az.y*gw4.y + az.z*gw4.z + az.w*gw4.w;
    #pragma unroll
    for (int off = 16; off; off >>= 1) p += __shfl_xor_sync(~0u, p, off);
    const float zv = d_hdot[row] + p;
    const float coeff = 1.0f / (1.0f + __expf(-zv));
    const float om = 1.0f - coeff;
    float4 h4 = *(const float4*)&d_h[(size_t)row*Dn + lane*4];
    float4 o4;
    o4.x = coeff*h4.x + om*az.x;
    o4.y = coeff*h4.y + om*az.y;
    o4.z = coeff*h4.z + om*az.z;
    o4.w = coeff*h4.w + om*az.w;
    *(float4*)&rout[(size_t)row*Dn + lane*4] = o4;
}

// ---------------- launch ----------------
extern "C" void kernel_launch(void* const* d_in, const int* in_sizes, int n_in,
                              void* d_out, int out_size) {
    const float* x   = (const float*)d_in[0];
    const float* adj = (const float*)d_in[1];
    const float* Ww  = (const float*)d_in[2];
    const float* Wb  = (const float*)d_in[3];
    const float* A   = (const float*)d_in[4];
    const float* gw  = (const float*)d_in[5];
    const float* gb  = (const float*)d_in[6];
    float* out = (float*)d_out;

    cudaFuncSetAttribute(k_h, cudaFuncAttributeMaxDynamicSharedMemorySize, HG_SMEM);
    cudaFuncSetAttribute(k_g, cudaFuncAttributeMaxDynamicSharedMemorySize, HG_SMEM);

    k_init<<<64, 256>>>();
    k_h<<<HG_GRID, 128, HG_SMEM>>>(x, Ww, Wb);
    k_g<<<HG_GRID, 128, HG_SMEM>>>(A, gw, gb);
    k_buildE<<<dim3(Nn, Bn), 128>>>(adj);
    k_colfinal<<<64, 256>>>();
    k_hop<<<2048, 256>>>(0, gw, out, 1);
    k_hop<<<2048, 256>>>(1, gw, out, 0);
    k_hop<<<2048, 256>>>(2, gw, out, 0);
}

// round 6
// speedup vs baseline: 2.2293x; 1.1359x over previous
#include <cuda_runtime.h>
#include <cuda_fp16.h>
#include <math.h>

#define Bn   16
#define Nn   1024
#define Dn   128
#define CAP  256     // max edges per row (mean ~52)

// ---------------- scratch (static device globals; no allocation) ----------------
__device__ float  d_h   [Bn*Nn*Dn];
__device__ __half d_hh  [Bn*Nn*Dn];    // half copy of h for gathers
__device__ float  d_g   [Bn*Nn*Dn];    // g' = h (A + A^T)
__device__ float  d_hdot[Bn*Nn];
__device__ int    d_colidx[Bn*Nn*CAP];
__device__ float  d_eval  [Bn*Nn*CAP];
__device__ int    d_rowcnt[Bn*Nn];
__device__ float  d_colZ  [Bn*Nn];
__device__ float  d_colinv[Bn*Nn];
__device__ __half d_r1h[Bn*Nn*Dn];
__device__ __half d_r2h[Bn*Nn*Dn];

// ---------------- init: colZ starts at N (non-edges contribute exp(0)=1;
// edges add exp(e)-1) ----------------
__global__ void k_init() {
    int t = blockIdx.x * blockDim.x + threadIdx.x;
    if (t < Bn*Nn) d_colZ[t] = (float)Nn;
}

// ---------------- k_h: h = x W^T + b (fp32 + half copy) ----------------
#define HG_GRID  410          // 410*40 = 16400 >= 16384
#define HG_SMEM  ((128*132 + 8*128)*4)

__global__ void k_h(const float* __restrict__ x, const float* __restrict__ Ww,
                    const float* __restrict__ Wb) {
    extern __shared__ float sm[];
    float* Ws = sm;               // [128][132] W row-major, padded
    float* xs = sm + 128*132;     // 8 rows of x

    const int t = threadIdx.x;    // 128 threads
    for (int i = t; i < 128*128; i += 128)
        Ws[(i >> 7)*132 + (i & 127)] = Ww[i];
    const float bo = Wb[t];
    const int r0base = blockIdx.x * 40;

    for (int it = 0; it < 5; it++) {
        const int r0 = r0base + it*8;
        __syncthreads();
        #pragma unroll
        for (int q = 0; q < 2; q++) {
            int idx = t + q*128;              // 0..255
            int rr = idx >> 5, wi = idx & 31;
            int row = r0 + rr;
            float4 v = make_float4(0,0,0,0);
            if (row < Bn*Nn) v = *(const float4*)&x[(size_t)row*Dn + wi*4];
            *(float4*)&xs[rr*128 + wi*4] = v;
        }
        __syncthreads();

        float acc[8];
        #pragma unroll
        for (int r = 0; r < 8; r++) acc[r] = bo;
        #pragma unroll 4
        for (int d4 = 0; d4 < 32; d4++) {
            float4 w4 = *(float4*)&Ws[t*132 + d4*4];
            #pragma unroll
            for (int r = 0; r < 8; r++) {
                float4 x4 = *(float4*)&xs[r*128 + d4*4];
                acc[r] += x4.x*w4.x + x4.y*w4.y + x4.z*w4.z + x4.w*w4.w;
            }
        }
        #pragma unroll
        for (int r = 0; r < 8; r++) {
            int row = r0 + r;
            if (row < Bn*Nn) {
                d_h [(size_t)row*Dn + t] = acc[r];
                d_hh[(size_t)row*Dn + t] = __float2half_rn(acc[r]);
            }
        }
    }
}

// ---------------- k_g: g' = h (A + A^T) ; hdot = h.gw[0:128] + gb ----------------
__global__ void k_g(const float* __restrict__ Am, const float* __restrict__ gw,
                    const float* __restrict__ gb) {
    extern __shared__ float sm[];
    float* As = sm;               // As[o][dd] = A[dd][o] + A[o][dd], padded 132
    float* hs = sm + 128*132;     // 8 rows of h

    const int t = threadIdx.x, lane = t & 31, warp = t >> 5;
    for (int i = t; i < 128*128; i += 128) {
        int dd = i >> 7, o = i & 127;
        As[o*132 + dd] = Am[i] + Am[o*128 + dd];
    }
    const float4 gw4 = *(const float4*)&gw[lane*4];
    const float gb0 = gb[0];
    const int r0base = blockIdx.x * 40;

    for (int it = 0; it < 5; it++) {
        const int r0 = r0base + it*8;
        __syncthreads();
        #pragma unroll
        for (int q = 0; q < 2; q++) {
            int idx = t + q*128;
            int rr = idx >> 5, wi = idx & 31;
            int row = r0 + rr;
            float4 v = make_float4(0,0,0,0);
            if (row < Bn*Nn) v = *(const float4*)&d_h[(size_t)row*Dn + wi*4];
            *(float4*)&hs[rr*128 + wi*4] = v;
        }
        __syncthreads();

        float acc[8];
        #pragma unroll
        for (int r = 0; r < 8; r++) acc[r] = 0.0f;
        #pragma unroll 4
        for (int d4 = 0; d4 < 32; d4++) {
            float4 a4 = *(float4*)&As[t*132 + d4*4];
            #pragma unroll
            for (int r = 0; r < 8; r++) {
                float4 h4 = *(float4*)&hs[r*128 + d4*4];
                acc[r] += h4.x*a4.x + h4.y*a4.y + h4.z*a4.z + h4.w*a4.w;
            }
        }
        #pragma unroll
        for (int r = 0; r < 8; r++) {
            int row = r0 + r;
            if (row < Bn*Nn) d_g[(size_t)row*Dn + t] = acc[r];
        }

        #pragma unroll
        for (int rr = 0; rr < 2; rr++) {
            int r = warp*2 + rr;
            int row = r0 + r;
            float4 h4 = *(float4*)&hs[r*128 + lane*4];
            float p = h4.x*gw4.x + h4.y*gw4.y + h4.z*gw4.z + h4.w*gw4.w;
            #pragma unroll
            for (int off = 16; off; off >>= 1) p += __shfl_xor_sync(~0u, p, off);
            if (lane == 0 && row < Bn*Nn) d_hdot[row] = p + gb0;
        }
    }
}

// ---------------- fused: CSR build + edge score (g'_row . h_col, half gather) + exp + colZ ----------------
__global__ void k_buildE(const float* __restrict__ adj) {
    const int i = blockIdx.x, b = blockIdx.y;
    const int row = b*Nn + i;
    __shared__ int   cols[CAP];
    __shared__ float P[128];      // g'_row fp32
    __shared__ int   cnt;
    const int t = threadIdx.x, lane = t & 31, warp = t >> 5;
    if (t == 0) cnt = 0;
    P[t] = d_g[(size_t)row*Dn + t];
    __syncthreads();

    // warp-aggregated CSR build
    const unsigned ltmask = (1u << lane) - 1u;
    const float4* a4 = (const float4*)(adj + (size_t)row * Nn);
    #pragma unroll
    for (int q = 0; q < 2; q++) {
        int idx = t + q*128;
        float4 v = a4[idx];
        #pragma unroll
        for (int c = 0; c < 4; c++) {
            float val = (c == 0) ? v.x : (c == 1) ? v.y : (c == 2) ? v.z : v.w;
            bool hit = val > 0.0f;
            unsigned m = __ballot_sync(~0u, hit);
            int base = 0;
            if (lane == 0 && m) base = atomicAdd(&cnt, __popc(m));
            base = __shfl_sync(~0u, base, 0);
            if (hit) {
                int s = base + __popc(m & ltmask);
                if (s < CAP) cols[s] = idx*4 + c;
            }
        }
    }
    __syncthreads();
    const int n  = (cnt < CAP) ? cnt : CAP;
    const int n8 = (n + 7) & ~7;            // padded length for hop kernels
    if (t == 0) d_rowcnt[row] = n8;
    for (int s = t; s < n; s += 128) d_colidx[(size_t)row*CAP + s] = cols[s];
    for (int s = n + t; s < n8; s += 128) {  // zero padding
        d_colidx[(size_t)row*CAP + s] = 0;
        d_eval  [(size_t)row*CAP + s] = 0.0f;
    }

    // g'_row slice: 8-lane groups, lane lo8 owns dims {k*64 + lo8*8 .. +7}, k=0,1
    const int lo8 = lane & 7, grp = lane >> 3;
    float rgv[16];
    #pragma unroll
    for (int k = 0; k < 2; k++)
        #pragma unroll
        for (int j = 0; j < 8; j++)
            rgv[k*8+j] = P[k*64 + lo8*8 + j];

    const __half* hb = d_hh + (size_t)b*Nn*Dn;
    for (int s0 = warp*4; s0 < n; s0 += 32) {
        const int sA = s0 + grp, sB = sA + 16;
        const int cA = cols[(sA < n) ? sA : 0];
        const int cB = cols[(sB < n) ? sB : 0];
        uint4 a0 = *(const uint4*)&hb[(size_t)cA*Dn +      lo8*8];
        uint4 a1 = *(const uint4*)&hb[(size_t)cA*Dn + 64 + lo8*8];
        uint4 b0 = *(const uint4*)&hb[(size_t)cB*Dn +      lo8*8];
        uint4 b1 = *(const uint4*)&hb[(size_t)cB*Dn + 64 + lo8*8];
        const __half2* ha0 = (const __half2*)&a0;
        const __half2* ha1 = (const __half2*)&a1;
        const __half2* hb0 = (const __half2*)&b0;
        const __half2* hb1 = (const __half2*)&b1;
        float pA = 0.0f, pB = 0.0f;
        #pragma unroll
        for (int j = 0; j < 4; j++) {
            float2 fa0 = __half22float2(ha0[j]);
            float2 fa1 = __half22float2(ha1[j]);
            float2 fb0 = __half22float2(hb0[j]);
            float2 fb1 = __half22float2(hb1[j]);
            pA += rgv[j*2]*fa0.x + rgv[j*2+1]*fa0.y + rgv[8+j*2]*fa1.x + rgv[8+j*2+1]*fa1.y;
            pB += rgv[j*2]*fb0.x + rgv[j*2+1]*fb0.y + rgv[8+j*2]*fb1.x + rgv[8+j*2+1]*fb1.y;
        }
        pA += __shfl_xor_sync(~0u, pA, 1); pB += __shfl_xor_sync(~0u, pB, 1);
        pA += __shfl_xor_sync(~0u, pA, 2); pB += __shfl_xor_sync(~0u, pB, 2);
        pA += __shfl_xor_sync(~0u, pA, 4); pB += __shfl_xor_sync(~0u, pB, 4);
        if (lo8 == 0) {
            if (sA < n) {
                float ev = __expf(pA);
                d_eval[(size_t)row*CAP + sA] = ev;
                atomicAdd(&d_colZ[b*Nn + cA], ev - 1.0f);
            }
            if (sB < n) {
                float ev = __expf(pB);
                d_eval[(size_t)row*CAP + sB] = ev;
                atomicAdd(&d_colZ[b*Nn + cB], ev - 1.0f);
            }
        }
    }
}

// ---------------- finalize: colinv = 1 / Z ----------------
__global__ void k_colfinal() {
    int t = blockIdx.x * blockDim.x + threadIdx.x;
    if (t < Bn*Nn)
        d_colinv[t] = 1.0f / d_colZ[t];
}

// ---------------- hop: warp/row, half gathers, 16-lane x 8-dim ownership ----------------
__global__ void k_hop(int which, const float* __restrict__ gw, float* __restrict__ outbuf,
                      int norm) {
    const __half* rin = (which == 0) ? d_hh : (which == 1 ? d_r1h : d_r2h);
    __half* routh = (which == 0) ? d_r1h : d_r2h;

    const int lane = threadIdx.x & 31, warp = threadIdx.x >> 5;
    const int row  = blockIdx.x * 8 + warp;
    const int b    = row >> 10;
    const int hw   = lane >> 4;     // half-warp id: picks edge parity
    const int lo   = lane & 15;     // owns dims lo*8 .. lo*8+7

    const __half* rb = rin + (size_t)b * Nn * Dn;
    const int    n8  = d_rowcnt[row];          // already padded to multiple of 8
    const int*   ci  = d_colidx + (size_t)row * CAP;
    float*       ev  = d_eval   + (size_t)row * CAP;
    const float* cinv = d_colinv + b*Nn;

    float acc[8];
    #pragma unroll
    for (int j = 0; j < 8; j++) acc[j] = 0.0f;

    for (int s = 0; s < n8; s += 8) {
        #pragma unroll
        for (int u = 0; u < 4; u++) {
            const int sx = s + u*2 + hw;
            const int c  = ci[sx];
            float v = ev[sx];
            if (norm) {
                v *= cinv[c];
                if (lo == 0) ev[sx] = v;
            }
            uint4 raw = *(const uint4*)&rb[(size_t)c*Dn + lo*8];
            const __half2* h2 = (const __half2*)&raw;
            #pragma unroll
            for (int j = 0; j < 4; j++) {
                float2 f = __half22float2(h2[j]);
                acc[j*2]   += v * f.x;
                acc[j*2+1] += v * f.y;
            }
        }
    }

    // combine the two half-warps (same dims, different edges)
    #pragma unroll
    for (int j = 0; j < 8; j++) acc[j] += __shfl_down_sync(~0u, acc[j], 16);

    float az[8];
    #pragma unroll
    for (int j = 0; j < 8; j++) az[j] = fmaxf(acc[j], 0.0f);

    // gate dot over the 16 low lanes (high lanes compute garbage, unused)
    float p = 0.0f;
    #pragma unroll
    for (int j = 0; j < 8; j++) p += az[j] * gw[128 + lo*8 + j];
    p += __shfl_xor_sync(~0u, p, 8);
    p += __shfl_xor_sync(~0u, p, 4);
    p += __shfl_xor_sync(~0u, p, 2);
    p += __shfl_xor_sync(~0u, p, 1);

    const float zv = d_hdot[row] + p;
    const float coeff = 1.0f / (1.0f + __expf(-zv));
    const float om = 1.0f - coeff;

    if (hw == 0) {
        float4 h4a = *(const float4*)&d_h[(size_t)row*Dn + lo*8];
        float4 h4b = *(const float4*)&d_h[(size_t)row*Dn + lo*8 + 4];
        float o[8];
        o[0] = coeff*h4a.x + om*az[0];
        o[1] = coeff*h4a.y + om*az[1];
        o[2] = coeff*h4a.z + om*az[2];
        o[3] = coeff*h4a.w + om*az[3];
        o[4] = coeff*h4b.x + om*az[4];
        o[5] = coeff*h4b.y + om*az[5];
        o[6] = coeff*h4b.z + om*az[6];
        o[7] = coeff*h4b.w + om*az[7];
        if (which == 2) {
            *(float4*)&outbuf[(size_t)row*Dn + lo*8]     = make_float4(o[0],o[1],o[2],o[3]);
            *(float4*)&outbuf[(size_t)row*Dn + lo*8 + 4] = make_float4(o[4],o[5],o[6],o[7]);
        } else {
            __half2 q0 = __floats2half2_rn(o[0], o[1]);
            __half2 q1 = __floats2half2_rn(o[2], o[3]);
            __half2 q2 = __floats2half2_rn(o[4], o[5]);
            __half2 q3 = __floats2half2_rn(o[6], o[7]);
            uint4 st;
            st.x = *reinterpret_cast<unsigned*>(&q0);
            st.y = *reinterpret_cast<unsigned*>(&q1);
            st.z = *reinterpret_cast<unsigned*>(&q2);
            st.w = *reinterpret_cast<unsigned*>(&q3);
            *(uint4*)&routh[(size_t)row*Dn + lo*8] = st;
        }
    }
}

// ---------------- launch ----------------
extern "C" void kernel_launch(void* const* d_in, const int* in_sizes, int n_in,
                              void* d_out, int out_size) {
    const float* x   = (const float*)d_in[0];
    const float* adj = (const float*)d_in[1];
    const float* Ww  = (const float*)d_in[2];
    const float* Wb  = (const float*)d_in[3];
    const float* A   = (const float*)d_in[4];
    const float* gw  = (const float*)d_in[5];
    const float* gb  = (const float*)d_in[6];
    float* out = (float*)d_out;

    cudaFuncSetAttribute(k_h, cudaFuncAttributeMaxDynamicSharedMemorySize, HG_SMEM);
    cudaFuncSetAttribute(k_g, cudaFuncAttributeMaxDynamicSharedMemorySize, HG_SMEM);

    k_init<<<64, 256>>>();
    k_h<<<HG_GRID, 128, HG_SMEM>>>(x, Ww, Wb);
    k_g<<<HG_GRID, 128, HG_SMEM>>>(A, gw, gb);
    k_buildE<<<dim3(Nn, Bn), 128>>>(adj);
    k_colfinal<<<64, 256>>>();
    k_hop<<<2048, 256>>>(0, gw, out, 1);
    k_hop<<<2048, 256>>>(1, gw, out, 0);
    k_hop<<<2048, 256>>>(2, gw, out, 0);
}

// round 7
// speedup vs baseline: 2.4343x; 1.0920x over previous
#include <cuda_runtime.h>
#include <cuda_fp16.h>
#include <math.h>

#define Bn   16
#define Nn   1024
#define Dn   128
#define CAP  256     // max edges per row (mean ~52)

// ---------------- scratch (static device globals; no allocation) ----------------
__device__ float  d_h   [Bn*Nn*Dn];
__device__ __half d_hh  [Bn*Nn*Dn];    // half copy of h for gathers
__device__ float  d_g   [Bn*Nn*Dn];    // g' = h (A + A^T)
__device__ float  d_hdot[Bn*Nn];
__device__ int    d_colidx[Bn*Nn*CAP];
__device__ float  d_eval  [Bn*Nn*CAP];
__device__ int    d_rowcnt[Bn*Nn];
__device__ float  d_colZ  [Bn*Nn];
__device__ float  d_colinv[Bn*Nn];
__device__ __half d_r1h[Bn*Nn*Dn];
__device__ __half d_r2h[Bn*Nn*Dn];

// ---------------- init: colZ starts at N ----------------
__global__ void k_init() {
    int t = blockIdx.x * blockDim.x + threadIdx.x;
    if (t < Bn*Nn) d_colZ[t] = (float)Nn;
}

// ================= dense GEMMs: 4 rows x 4 outs per thread =================
#define KH_ROWS  64
#define KH_GRID  (Bn*Nn/KH_ROWS)      // 256
#define KH_SMEM  ((128*132 + 16*128)*4)

// ---------------- k_h: h = x W^T + b (fp32 + half copy) ----------------
__global__ void k_h(const float* __restrict__ x, const float* __restrict__ Ww,
                    const float* __restrict__ Wb) {
    extern __shared__ float sm[];
    float* Wt = sm;               // [dim][out] transposed, padded 132
    float* xs = sm + 128*132;     // 16 rows of x

    const int t = threadIdx.x, lane = t & 31, warp = t >> 5;
    for (int i = t; i < 128*128; i += 128)
        Wt[(i & 127)*132 + (i >> 7)] = Ww[i];      // Wt[d][o] = W[o][d]
    const float4 bias = *(const float4*)&Wb[lane*4];
    const int rowbase = blockIdx.x * KH_ROWS;

    for (int it = 0; it < KH_ROWS/16; it++) {
        const int r0 = rowbase + it*16;
        __syncthreads();
        #pragma unroll
        for (int q = 0; q < 4; q++) {
            int idx = t + q*128;                   // float4 index 0..511
            *(float4*)&xs[idx*4] = *(const float4*)&x[(size_t)r0*Dn + idx*4];
        }
        __syncthreads();

        float4 acc[4];
        #pragma unroll
        for (int r = 0; r < 4; r++) acc[r] = bias;

        #pragma unroll 4
        for (int d4 = 0; d4 < 32; d4++) {
            float4 w0 = *(float4*)&Wt[(d4*4+0)*132 + lane*4];
            float4 w1 = *(float4*)&Wt[(d4*4+1)*132 + lane*4];
            float4 w2 = *(float4*)&Wt[(d4*4+2)*132 + lane*4];
            float4 w3 = *(float4*)&Wt[(d4*4+3)*132 + lane*4];
            #pragma unroll
            for (int r = 0; r < 4; r++) {
                float4 xr = *(float4*)&xs[(warp*4+r)*128 + d4*4];
                acc[r].x += xr.x*w0.x + xr.y*w1.x + xr.z*w2.x + xr.w*w3.x;
                acc[r].y += xr.x*w0.y + xr.y*w1.y + xr.z*w2.y + xr.w*w3.y;
                acc[r].z += xr.x*w0.z + xr.y*w1.z + xr.z*w2.z + xr.w*w3.z;
                acc[r].w += xr.x*w0.w + xr.y*w1.w + xr.z*w2.w + xr.w*w3.w;
            }
        }
        #pragma unroll
        for (int r = 0; r < 4; r++) {
            const int row = r0 + warp*4 + r;
            *(float4*)&d_h[(size_t)row*Dn + lane*4] = acc[r];
            __half2 q0 = __floats2half2_rn(acc[r].x, acc[r].y);
            __half2 q1 = __floats2half2_rn(acc[r].z, acc[r].w);
            uint2 st;
            st.x = *reinterpret_cast<unsigned*>(&q0);
            st.y = *reinterpret_cast<unsigned*>(&q1);
            *(uint2*)&d_hh[(size_t)row*Dn + lane*4] = st;
        }
    }
}

// ---------------- k_g: g' = h (A + A^T) ; hdot = h.gw[0:128] + gb ----------------
__global__ void k_g(const float* __restrict__ Am, const float* __restrict__ gw,
                    const float* __restrict__ gb) {
    extern __shared__ float sm[];
    float* Ss = sm;               // S[d][o] = A[d][o] + A[o][d], padded 132
    float* hs = sm + 128*132;     // 16 rows of h

    const int t = threadIdx.x, lane = t & 31, warp = t >> 5;
    for (int i = t; i < 128*128; i += 128) {
        int d = i >> 7, o = i & 127;
        Ss[d*132 + o] = Am[i] + Am[o*128 + d];
    }
    const float4 gw4 = *(const float4*)&gw[lane*4];
    const float gb0 = gb[0];
    const int rowbase = blockIdx.x * KH_ROWS;

    for (int it = 0; it < KH_ROWS/16; it++) {
        const int r0 = rowbase + it*16;
        __syncthreads();
        #pragma unroll
        for (int q = 0; q < 4; q++) {
            int idx = t + q*128;
            *(float4*)&hs[idx*4] = *(const float4*)&d_h[(size_t)r0*Dn + idx*4];
        }
        __syncthreads();

        float4 acc[4];
        #pragma unroll
        for (int r = 0; r < 4; r++) acc[r] = make_float4(0,0,0,0);

        #pragma unroll 4
        for (int d4 = 0; d4 < 32; d4++) {
            float4 w0 = *(float4*)&Ss[(d4*4+0)*132 + lane*4];
            float4 w1 = *(float4*)&Ss[(d4*4+1)*132 + lane*4];
            float4 w2 = *(float4*)&Ss[(d4*4+2)*132 + lane*4];
            float4 w3 = *(float4*)&Ss[(d4*4+3)*132 + lane*4];
            #pragma unroll
            for (int r = 0; r < 4; r++) {
                float4 hr = *(float4*)&hs[(warp*4+r)*128 + d4*4];
                acc[r].x += hr.x*w0.x + hr.y*w1.x + hr.z*w2.x + hr.w*w3.x;
                acc[r].y += hr.x*w0.y + hr.y*w1.y + hr.z*w2.y + hr.w*w3.y;
                acc[r].z += hr.x*w0.z + hr.y*w1.z + hr.z*w2.z + hr.w*w3.z;
                acc[r].w += hr.x*w0.w + hr.y*w1.w + hr.z*w2.w + hr.w*w3.w;
            }
        }
        #pragma unroll
        for (int r = 0; r < 4; r++) {
            const int row = r0 + warp*4 + r;
            *(float4*)&d_g[(size_t)row*Dn + lane*4] = acc[r];
        }

        // hdot for this warp's 4 rows
        #pragma unroll
        for (int r = 0; r < 4; r++) {
            const int row = r0 + warp*4 + r;
            float4 h4 = *(float4*)&hs[(warp*4+r)*128 + lane*4];
            float p = h4.x*gw4.x + h4.y*gw4.y + h4.z*gw4.z + h4.w*gw4.w;
            #pragma unroll
            for (int off = 16; off; off >>= 1) p += __shfl_xor_sync(~0u, p, off);
            if (lane == 0) d_hdot[row] = p + gb0;
        }
    }
}

// ---------------- fused: CSR build + edge score (g'_row . h_col, half gather) + exp + colZ ----------------
__global__ void k_buildE(const float* __restrict__ adj) {
    const int i = blockIdx.x, b = blockIdx.y;
    const int row = b*Nn + i;
    __shared__ int   cols[CAP];
    __shared__ float P[128];      // g'_row fp32
    __shared__ int   cnt;
    const int t = threadIdx.x, lane = t & 31, warp = t >> 5;
    if (t == 0) cnt = 0;
    P[t] = d_g[(size_t)row*Dn + t];
    __syncthreads();

    // warp-aggregated CSR build
    const unsigned ltmask = (1u << lane) - 1u;
    const float4* a4 = (const float4*)(adj + (size_t)row * Nn);
    #pragma unroll
    for (int q = 0; q < 2; q++) {
        int idx = t + q*128;
        float4 v = a4[idx];
        #pragma unroll
        for (int c = 0; c < 4; c++) {
            float val = (c == 0) ? v.x : (c == 1) ? v.y : (c == 2) ? v.z : v.w;
            bool hit = val > 0.0f;
            unsigned m = __ballot_sync(~0u, hit);
            int base = 0;
            if (lane == 0 && m) base = atomicAdd(&cnt, __popc(m));
            base = __shfl_sync(~0u, base, 0);
            if (hit) {
                int s = base + __popc(m & ltmask);
                if (s < CAP) cols[s] = idx*4 + c;
            }
        }
    }
    __syncthreads();
    const int n  = (cnt < CAP) ? cnt : CAP;
    const int n8 = (n + 7) & ~7;            // padded length for hop kernels
    if (t == 0) d_rowcnt[row] = n8;
    for (int s = t; s < n; s += 128) d_colidx[(size_t)row*CAP + s] = cols[s];
    for (int s = n + t; s < n8; s += 128) {  // zero padding
        d_colidx[(size_t)row*CAP + s] = 0;
        d_eval  [(size_t)row*CAP + s] = 0.0f;
    }

    // g'_row slice: 8-lane groups, lane lo8 owns dims {k*64 + lo8*8 .. +7}, k=0,1
    const int lo8 = lane & 7, grp = lane >> 3;
    float rgv[16];
    #pragma unroll
    for (int k = 0; k < 2; k++)
        #pragma unroll
        for (int j = 0; j < 8; j++)
            rgv[k*8+j] = P[k*64 + lo8*8 + j];

    const __half* hb = d_hh + (size_t)b*Nn*Dn;
    for (int s0 = warp*4; s0 < n; s0 += 32) {
        const int sA = s0 + grp, sB = sA + 16;
        const int cA = cols[(sA < n) ? sA : 0];
        const int cB = cols[(sB < n) ? sB : 0];
        uint4 a0 = *(const uint4*)&hb[(size_t)cA*Dn +      lo8*8];
        uint4 a1 = *(const uint4*)&hb[(size_t)cA*Dn + 64 + lo8*8];
        uint4 b0 = *(const uint4*)&hb[(size_t)cB*Dn +      lo8*8];
        uint4 b1 = *(const uint4*)&hb[(size_t)cB*Dn + 64 + lo8*8];
        const __half2* ha0 = (const __half2*)&a0;
        const __half2* ha1 = (const __half2*)&a1;
        const __half2* hb0 = (const __half2*)&b0;
        const __half2* hb1 = (const __half2*)&b1;
        float pA = 0.0f, pB = 0.0f;
        #pragma unroll
        for (int j = 0; j < 4; j++) {
            float2 fa0 = __half22float2(ha0[j]);
            float2 fa1 = __half22float2(ha1[j]);
            float2 fb0 = __half22float2(hb0[j]);
            float2 fb1 = __half22float2(hb1[j]);
            pA += rgv[j*2]*fa0.x + rgv[j*2+1]*fa0.y + rgv[8+j*2]*fa1.x + rgv[8+j*2+1]*fa1.y;
            pB += rgv[j*2]*fb0.x + rgv[j*2+1]*fb0.y + rgv[8+j*2]*fb1.x + rgv[8+j*2+1]*fb1.y;
        }
        pA += __shfl_xor_sync(~0u, pA, 1); pB += __shfl_xor_sync(~0u, pB, 1);
        pA += __shfl_xor_sync(~0u, pA, 2); pB += __shfl_xor_sync(~0u, pB, 2);
        pA += __shfl_xor_sync(~0u, pA, 4); pB += __shfl_xor_sync(~0u, pB, 4);
        if (lo8 == 0) {
            if (sA < n) {
                float ev = __expf(pA);
                d_eval[(size_t)row*CAP + sA] = ev;
                atomicAdd(&d_colZ[b*Nn + cA], ev - 1.0f);
            }
            if (sB < n) {
                float ev = __expf(pB);
                d_eval[(size_t)row*CAP + sB] = ev;
                atomicAdd(&d_colZ[b*Nn + cB], ev - 1.0f);
            }
        }
    }
}

// ---------------- finalize: colinv = 1 / Z ----------------
__global__ void k_colfinal() {
    int t = blockIdx.x * blockDim.x + threadIdx.x;
    if (t < Bn*Nn)
        d_colinv[t] = 1.0f / d_colZ[t];
}

// ---------------- hop: warp/row, half gathers, 16-lane x 8-dim ownership ----------------
__global__ void k_hop(int which, const float* __restrict__ gw, float* __restrict__ outbuf,
                      int norm) {
    const __half* rin = (which == 0) ? d_hh : (which == 1 ? d_r1h : d_r2h);
    __half* routh = (which == 0) ? d_r1h : d_r2h;

    const int lane = threadIdx.x & 31, warp = threadIdx.x >> 5;
    const int row  = blockIdx.x * 8 + warp;
    const int b    = row >> 10;
    const int hw   = lane >> 4;     // half-warp id: picks edge parity
    const int lo   = lane & 15;     // owns dims lo*8 .. lo*8+7

    const __half* rb = rin + (size_t)b * Nn * Dn;
    const int    n8  = d_rowcnt[row];          // already padded to multiple of 8
    const int*   ci  = d_colidx + (size_t)row * CAP;
    float*       ev  = d_eval   + (size_t)row * CAP;
    const float* cinv = d_colinv + b*Nn;

    float acc[8];
    #pragma unroll
    for (int j = 0; j < 8; j++) acc[j] = 0.0f;

    for (int s = 0; s < n8; s += 8) {
        #pragma unroll
        for (int u = 0; u < 4; u++) {
            const int sx = s + u*2 + hw;
            const int c  = ci[sx];
            float v = ev[sx];
            if (norm) {
                v *= cinv[c];
                if (lo == 0) ev[sx] = v;
            }
            uint4 raw = *(const uint4*)&rb[(size_t)c*Dn + lo*8];
            const __half2* h2 = (const __half2*)&raw;
            #pragma unroll
            for (int j = 0; j < 4; j++) {
                float2 f = __half22float2(h2[j]);
                acc[j*2]   += v * f.x;
                acc[j*2+1] += v * f.y;
            }
        }
    }

    // combine the two half-warps (same dims, different edges)
    #pragma unroll
    for (int j = 0; j < 8; j++) acc[j] += __shfl_down_sync(~0u, acc[j], 16);

    float az[8];
    #pragma unroll
    for (int j = 0; j < 8; j++) az[j] = fmaxf(acc[j], 0.0f);

    // gate dot over the 16 low lanes
    float p = 0.0f;
    #pragma unroll
    for (int j = 0; j < 8; j++) p += az[j] * gw[128 + lo*8 + j];
    p += __shfl_xor_sync(~0u, p, 8);
    p += __shfl_xor_sync(~0u, p, 4);
    p += __shfl_xor_sync(~0u, p, 2);
    p += __shfl_xor_sync(~0u, p, 1);

    const float zv = d_hdot[row] + p;
    const float coeff = 1.0f / (1.0f + __expf(-zv));
    const float om = 1.0f - coeff;

    if (hw == 0) {
        float4 h4a = *(const float4*)&d_h[(size_t)row*Dn + lo*8];
        float4 h4b = *(const float4*)&d_h[(size_t)row*Dn + lo*8 + 4];
        float o[8];
        o[0] = coeff*h4a.x + om*az[0];
        o[1] = coeff*h4a.y + om*az[1];
        o[2] = coeff*h4a.z + om*az[2];
        o[3] = coeff*h4a.w + om*az[3];
        o[4] = coeff*h4b.x + om*az[4];
        o[5] = coeff*h4b.y + om*az[5];
        o[6] = coeff*h4b.z + om*az[6];
        o[7] = coeff*h4b.w + om*az[7];
        if (which == 2) {
            *(float4*)&outbuf[(size_t)row*Dn + lo*8]     = make_float4(o[0],o[1],o[2],o[3]);
            *(float4*)&outbuf[(size_t)row*Dn + lo*8 + 4] = make_float4(o[4],o[5],o[6],o[7]);
        } else {
            __half2 q0 = __floats2half2_rn(o[0], o[1]);
            __half2 q1 = __floats2half2_rn(o[2], o[3]);
            __half2 q2 = __floats2half2_rn(o[4], o[5]);
            __half2 q3 = __floats2half2_rn(o[6], o[7]);
            uint4 st;
            st.x = *reinterpret_cast<unsigned*>(&q0);
            st.y = *reinterpret_cast<unsigned*>(&q1);
            st.z = *reinterpret_cast<unsigned*>(&q2);
            st.w = *reinterpret_cast<unsigned*>(&q3);
            *(uint4*)&routh[(size_t)row*Dn + lo*8] = st;
        }
    }
}

// ---------------- launch ----------------
extern "C" void kernel_launch(void* const* d_in, const int* in_sizes, int n_in,
                              void* d_out, int out_size) {
    const float* x   = (const float*)d_in[0];
    const float* adj = (const float*)d_in[1];
    const float* Ww  = (const float*)d_in[2];
    const float* Wb  = (const float*)d_in[3];
    const float* A   = (const float*)d_in[4];
    const float* gw  = (const float*)d_in[5];
    const float* gb  = (const float*)d_in[6];
    float* out = (float*)d_out;

    cudaFuncSetAttribute(k_h, cudaFuncAttributeMaxDynamicSharedMemorySize, KH_SMEM);
    cudaFuncSetAttribute(k_g, cudaFuncAttributeMaxDynamicSharedMemorySize, KH_SMEM);

    k_init<<<64, 256>>>();
    k_h<<<KH_GRID, 128, KH_SMEM>>>(x, Ww, Wb);
    k_g<<<KH_GRID, 128, KH_SMEM>>>(A, gw, gb);
    k_buildE<<<dim3(Nn, Bn), 128>>>(adj);
    k_colfinal<<<64, 256>>>();
    k_hop<<<2048, 256>>>(0, gw, out, 1);
    k_hop<<<2048, 256>>>(1, gw, out, 0);
    k_hop<<<2048, 256>>>(2, gw, out, 0);
}